// round 12
// baseline (speedup 1.0000x reference)
#include <cuda_runtime.h>
#include <math.h>

#define Bb 128
#define Ss 128
#define Nn 196
#define Dd 512
#define D2 1024
#define Tt 12
#define N3 1536

#define NB 128
#define NTH 512

#define ZP 8       // p GEMM split-K (K=128 chunks)
#define ZB 4       // Wrm@Wwc split-K
#define Z2 4       // P2 split-K
#define ZC 4       // comb split-K
#define ZW 8       // write split-K

// ---------------- device scratch ----------------
__device__ float g_pp   [ZP * Bb * Tt * Dd];
__device__ float g_pfull[Bb * Tt * Dd];
__device__ float g_P2p  [Z2 * Bb * Tt * Dd];
__device__ float g_cbp  [ZC * Bb * N3];
__device__ float g_fpA  [ZW * Bb * D2];
__device__ float g_fpB  [ZW * Bb * D2];
__device__ float g_BcP  [ZB * Dd * D2];
__device__ float g_BcF  [Dd * D2];
__device__ float g_bp2  [Tt * Dd];
__device__ float g_c    [Bb * Dd];
__device__ float g_m0   [Bb * Dd];
__device__ float g_mf   [Bb * Dd];
__device__ float g_r    [Bb * Dd];
__device__ float g_bias2[Dd];
__device__ float g_mmrow[Dd];

__device__ int          g_bar_count = 0;
__device__ volatile int g_bar_gen   = 0;

// ---------------- helpers ----------------
__device__ __forceinline__ float warp_sum(float v) {
#pragma unroll
    for (int o = 16; o; o >>= 1) v += __shfl_xor_sync(0xffffffffu, v, o);
    return v;
}
__device__ __forceinline__ float warp_max(float v) {
#pragma unroll
    for (int o = 16; o; o >>= 1) v = fmaxf(v, __shfl_xor_sync(0xffffffffu, v, o));
    return v;
}

__device__ __forceinline__ unsigned long long splat2(float x) {
    unsigned long long r;
    asm("mov.b64 %0, {%1, %1};" : "=l"(r) : "f"(x));
    return r;
}
__device__ __forceinline__ void ffma2(unsigned long long& d,
                                      unsigned long long a, unsigned long long b) {
    asm("fma.rn.f32x2 %0, %1, %2, %0;" : "+l"(d) : "l"(a), "l"(b));
}
__device__ __forceinline__ void unpack2(unsigned long long v, float& lo, float& hi) {
    asm("mov.b64 {%0, %1}, %2;" : "=f"(lo), "=f"(hi) : "l"(v));
}

// grid barrier: all NB blocks co-resident by construction
__device__ __forceinline__ void grid_sync(int& gen) {
    __syncthreads();
    if (threadIdx.x == 0) {
        __threadfence();
        if (atomicAdd(&g_bar_count, 1) == NB - 1) {
            g_bar_count = 0;
            __threadfence();
            g_bar_gen = gen + 1;
        } else {
            while ((int)(g_bar_gen - gen) <= 0) { }
        }
        __threadfence();
    }
    __syncthreads();
    gen++;
}

// ---------------- GEMM tile: C[128,128] = A[128,klen] * B^T, f32x2 FMA -------
// B(n,k) = B[n*ldbN + k*ldbK] (+optional per-k scale ks on NN path).
// 512 threads: warp ty handles m rows ty*8..+7 (as 4 f32x2 pairs), lane tx
// handles n cols tx*4..+3.
__device__ void gemm_tile(const float* __restrict__ A, int lda,
                          const float* __restrict__ B, int ldbN, int ldbK,
                          const float* __restrict__ ks,
                          float* __restrict__ C, int ldc, int klen,
                          float* __restrict__ sh)
{
    float* As = sh;              // [16][132]
    float* Bs = sh + 16 * 132;   // [16][132]
    const int tid = threadIdx.x;
    const int ty = tid >> 5, tx = tid & 31;
    const int aRow = tid >> 2, aK4 = (tid & 3) << 2;   // A + B-NT loader map
    const int bK = tid >> 5, bN4 = (tid & 31) << 2;    // B-NN loader map
    const bool nt = (ldbK == 1);

    unsigned long long acc[4][4];
#pragma unroll
    for (int i = 0; i < 4; i++)
#pragma unroll
        for (int j = 0; j < 4; j++) acc[i][j] = 0ull;

    float4 ra, rb;
    ra = *(const float4*)(A + (size_t)aRow * lda + aK4);
    if (nt) {
        rb = *(const float4*)(B + (size_t)aRow * ldbN + aK4);
    } else {
        rb = *(const float4*)(B + (size_t)bK * ldbK + bN4);
        if (ks) { float s = ks[bK]; rb.x *= s; rb.y *= s; rb.z *= s; rb.w *= s; }
    }

    for (int k0 = 0; k0 < klen; k0 += 16) {
        As[(aK4 + 0) * 132 + aRow] = ra.x;
        As[(aK4 + 1) * 132 + aRow] = ra.y;
        As[(aK4 + 2) * 132 + aRow] = ra.z;
        As[(aK4 + 3) * 132 + aRow] = ra.w;
        if (nt) {
            Bs[(aK4 + 0) * 132 + aRow] = rb.x;
            Bs[(aK4 + 1) * 132 + aRow] = rb.y;
            Bs[(aK4 + 2) * 132 + aRow] = rb.z;
            Bs[(aK4 + 3) * 132 + aRow] = rb.w;
        } else {
            *(float4*)(Bs + bK * 132 + bN4) = rb;
        }
        __syncthreads();

        if (k0 + 16 < klen) {
            int kn = k0 + 16;
            ra = *(const float4*)(A + (size_t)aRow * lda + kn + aK4);
            if (nt) {
                rb = *(const float4*)(B + (size_t)aRow * ldbN + kn + aK4);
            } else {
                rb = *(const float4*)(B + (size_t)(kn + bK) * ldbK + bN4);
                if (ks) { float s = ks[kn + bK]; rb.x *= s; rb.y *= s; rb.z *= s; rb.w *= s; }
            }
        }

#pragma unroll
        for (int kk = 0; kk < 16; kk++) {
            double2 a01 = *(const double2*)(As + kk * 132 + ty * 8);
            double2 a23 = *(const double2*)(As + kk * 132 + ty * 8 + 4);
            float4  bf  = *(const float4*)(Bs + kk * 132 + tx * 4);
            unsigned long long am[4];
            am[0] = __double_as_longlong(a01.x);
            am[1] = __double_as_longlong(a01.y);
            am[2] = __double_as_longlong(a23.x);
            am[3] = __double_as_longlong(a23.y);
            unsigned long long bs4[4];
            bs4[0] = splat2(bf.x); bs4[1] = splat2(bf.y);
            bs4[2] = splat2(bf.z); bs4[3] = splat2(bf.w);
#pragma unroll
            for (int i = 0; i < 4; i++)
#pragma unroll
                for (int j = 0; j < 4; j++) ffma2(acc[i][j], am[i], bs4[j]);
        }
        __syncthreads();
    }

#pragma unroll
    for (int i = 0; i < 4; i++) {
        float lo[4], hi[4];
#pragma unroll
        for (int j = 0; j < 4; j++) unpack2(acc[i][j], lo[j], hi[j]);
        int m0 = ty * 8 + 2 * i;
        *(float4*)(C + (size_t)m0 * ldc + tx * 4)       = make_float4(lo[0], lo[1], lo[2], lo[3]);
        *(float4*)(C + (size_t)(m0 + 1) * ldc + tx * 4) = make_float4(hi[0], hi[1], hi[2], hi[3]);
    }
}

// comb job: z in [0,ZC), nI in [0,12): c @ [Wra*Wrc^T ; Wcq1]^T chunk
__device__ __forceinline__ void do_comb(int z, int nI,
                                        const float* __restrict__ Wrc,
                                        const float* __restrict__ Wra,
                                        const float* __restrict__ Wcq,
                                        float* sh)
{
    int kbeg = z * 128, bn = nI * 128;
    if (bn < D2) {
        gemm_tile(g_c + kbeg, Dd,
                  Wrc + (size_t)kbeg * D2 + bn, 1, D2, Wra + kbeg,
                  g_cbp + (size_t)z * (Bb * N3) + bn, N3, 128, sh);
    } else {
        gemm_tile(g_c + kbeg, Dd,
                  Wcq + (size_t)(bn - D2) * D2 + kbeg, D2, 1, nullptr,
                  g_cbp + (size_t)z * (Bb * N3) + bn, N3, 128, sh);
    }
}

// write job: z in [0,ZW), nI in [0,8): concat(r, m_tw) @ [Wwc ; Wrm@Wwc]^T
__device__ __forceinline__ void do_write(int tw, int z, int nI,
                                         const float* __restrict__ Wwc,
                                         float* sh)
{
    int kbeg = z * 128, bn = nI * 128;
    const float* A = (kbeg < Dd) ? (g_r + kbeg)
                                 : ((tw == 0 ? g_m0 : g_mf) + (kbeg - Dd));
    const float* Bp = (bn < Dd) ? (Wwc + (size_t)bn * D2 + kbeg)
                                : (g_BcF + (size_t)(bn - Dd) * D2 + kbeg);
    float* fp = (tw & 1) ? g_fpB : g_fpA;
    gemm_tile(A, Dd, Bp, D2, 1, nullptr,
              fp + (size_t)z * (Bb * D2) + bn, D2, 128, sh);
}

// ---------------- persistent mega-kernel ----------------
__global__ void __launch_bounds__(NTH, 1) mac_mega(
    const float* __restrict__ ctx, const float* __restrict__ q,
    const float* __restrict__ kten, const float* __restrict__ mem0,
    const float* __restrict__ ctrl0, const float* __restrict__ Wp,
    const float* __restrict__ bp, const float* __restrict__ Wcq,
    const float* __restrict__ bcq, const float* __restrict__ Wca,
    const float* __restrict__ Wrm, const float* __restrict__ brm,
    const float* __restrict__ Wrc, const float* __restrict__ Wra,
    const float* __restrict__ Wwc, const float* __restrict__ bwc,
    float* __restrict__ out)
{
    __shared__ __align__(16) float sh[2 * 16 * 132];
    __shared__ __align__(16) float us[Dd];
    __shared__ float sl[Ss];
    __shared__ float rw0[256];
    __shared__ float rw1[256];
    __shared__ float red;

    const int bid = blockIdx.x;
    const int tid = threadIdx.x;
    const int lane = tid & 31, wrp = tid >> 5;
    int gen = g_bar_gen;

    // ===== S1: init + small dots + p GEMM (384 jobs) + Wrm@Wwc (128 jobs) =====
    {
        int i = bid * NTH + tid;
        g_c[i]  = ctrl0[i & (Dd - 1)];
        g_m0[i] = mem0[i & (Dd - 1)];
    }
    for (int job = bid * 16 + wrp; job < 512 + Tt * Dd; job += NB * 16) {
        if (job < 512) {
            int d = job;
            const float* row = Wrm + (size_t)d * Dd;
            float s1 = 0.f, s2 = 0.f;
            for (int j = lane; j < Dd; j += 32) { float x = row[j]; s1 += x * bwc[j]; s2 += x * mem0[j]; }
            s1 = warp_sum(s1); s2 = warp_sum(s2);
            if (lane == 0) { g_bias2[d] = brm[d] + s1; g_mmrow[d] = brm[d] + s2; }
        } else {
            int idx = job - 512; int t = idx >> 9, d = idx & 511;
            float s = 0.f;
            for (int j = lane; j < Dd; j += 32) s += bp[t * Dd + j] * Wcq[(size_t)d * D2 + Dd + j];
            s = warp_sum(s);
            if (lane == 0) g_bp2[t * Dd + d] = s;
        }
    }
    for (int j = bid; j < 384 + 128; j += NB) {
        if (j < 384) {
            int z = j / 48, nI = j % 48;
            gemm_tile(q + z * 128, D2,
                      Wp + (size_t)(nI * 128) * D2 + z * 128, D2, 1, nullptr,
                      g_pp + (size_t)z * (Bb * Tt * Dd) + nI * 128, Tt * Dd, 128, sh);
        } else {
            int r = j - 384; int z = r >> 5, mI = (r >> 3) & 3, nI = r & 7;
            gemm_tile(Wrm + (size_t)(mI * 128) * Dd + z * 128, Dd,
                      Wwc + (size_t)(z * 128) * D2 + nI * 128, 1, D2, nullptr,
                      g_BcP + (size_t)z * (Dd * D2) + (size_t)(mI * 128) * D2 + nI * 128,
                      D2, 128, sh);
        }
    }
    grid_sync(gen);

    // ===== S1.5: reduce p and BcBot partials =====
    {
        const int tot = Bb * Tt * Dd;
        for (int i = bid * NTH + tid; i < tot; i += NB * NTH) {
            float v = 0.f;
#pragma unroll
            for (int z = 0; z < ZP; z++) v += g_pp[(size_t)z * tot + i];
            g_pfull[i] = v;
        }
        const int tot2 = Dd * D2;
        for (int i = bid * NTH + tid; i < tot2; i += NB * NTH) {
            float v = 0.f;
#pragma unroll
            for (int z = 0; z < ZB; z++) v += g_BcP[(size_t)z * tot2 + i];
            g_BcF[i] = v;
        }
    }
    grid_sync(gen);

    // ===== S2: P2 GEMM (192 jobs) + comb(c(-1)) u-half only (16 jobs) =====
    for (int j = bid; j < 192 + 16; j += NB) {
        if (j < 192) {
            int z = j / 48, r = j % 48, mI = r >> 2, nI = r & 3;
            gemm_tile(g_pfull + (size_t)(mI * 128) * Dd + z * 128, Dd,
                      Wcq + (size_t)(nI * 128) * D2 + Dd + z * 128, D2, 1, nullptr,
                      g_P2p + (size_t)z * (Bb * Tt * Dd) + (size_t)(mI * 128) * Dd + nI * 128,
                      Dd, 128, sh);
        } else {
            int r = j - 192;
            do_comb(r >> 2, 8 + (r & 3), Wrc, Wra, Wcq, sh);
        }
    }
    grid_sync(gen);

    // ===== A(-1): attn_ctx(0) =====
    for (int t = -1; t < Tt; t++) {
        const int b = bid, d = tid;
        if (t >= 0) {
            // ---- attn_k(t) (+ reduce mm(t), m(t)) ----
            float w2a = 0.f, w2b = 0.f;
#pragma unroll
            for (int z = 0; z < ZC; z++) {
                w2a += g_cbp[(size_t)z * (Bb * N3) + b * N3 + d];
                w2b += g_cbp[(size_t)z * (Bb * N3) + b * N3 + Dd + d];
            }
            float mmv;
            if (t == 0) {
                mmv = g_mmrow[d];
            } else {
                const float* fp = ((t - 1) & 1) ? g_fpB : g_fpA;
                float s1 = 0.f, mval = 0.f;
#pragma unroll
                for (int z = 0; z < ZW; z++) {
                    s1   += fp[(size_t)z * (Bb * D2) + b * D2 + Dd + d];
                    mval += fp[(size_t)z * (Bb * D2) + b * D2 + d];
                }
                mmv = s1 + g_bias2[d];
                g_mf[b * Dd + d] = mval + bwc[d];
            }
            us[d] = w2a * mmv + w2b;
            __syncthreads();

            const float* kb = kten + (size_t)b * Dd * Nn;
            {
                int half = tid >> 8, n = tid & 255;
                if (n < Nn) {
                    float acc = 0.f;
                    int j0 = half * 256;
#pragma unroll 8
                    for (int j2 = j0; j2 < j0 + 256; j2++) acc += us[j2] * kb[(size_t)j2 * Nn + n];
                    (half ? rw1 : rw0)[n] = acc;
                }
            }
            __syncthreads();
            if (tid < Nn) rw0[tid] += rw1[tid];
            __syncthreads();
            if (wrp == 0) {
                float mx = -1e30f;
                for (int i = lane; i < Nn; i += 32) mx = fmaxf(mx, rw0[i]);
                mx = warp_max(mx);
                float sm = 0.f;
                for (int i = lane; i < Nn; i += 32) { float e = __expf(rw0[i] - mx); rw0[i] = e; sm += e; }
                sm = warp_sum(sm);
                if (lane == 0) red = 1.f / sm;
            }
            __syncthreads();
            const float inv = red;
            for (int dd2 = wrp; dd2 < Dd; dd2 += 16) {
                const float* row = kb + (size_t)dd2 * Nn;
                float part = 0.f;
                for (int n = lane; n < Nn; n += 32) part += rw0[n] * row[n];
                part = warp_sum(part);
                if (lane == 0) g_r[b * Dd + dd2] = part * inv;
            }
            __syncthreads();
        }

        if (t + 1 < Tt) {
            // ---- attn_ctx(t+1) ----
            const int tc = t + 1;
            float v = 0.f;
#pragma unroll
            for (int z = 0; z < ZC; z++) v += g_cbp[(size_t)z * (Bb * N3) + b * N3 + D2 + d];
            float v2 = 0.f;
#pragma unroll
            for (int z = 0; z < Z2; z++) v2 += g_P2p[(size_t)z * (Bb * Tt * Dd) + (b * Tt + tc) * Dd + d];
            v += v2 + bcq[d] + g_bp2[tc * Dd + d];
            us[d] = v * Wca[d];
            __syncthreads();

            const float* cb = ctx + (size_t)b * Ss * Dd;
            const float4* us4 = (const float4*)us;
            for (int s = wrp; s < Ss; s += 16) {
                const float4* row4 = (const float4*)(cb + (size_t)s * Dd);
                float part = 0.f;
#pragma unroll
                for (int d4 = lane; d4 < Dd / 4; d4 += 32) {
                    float4 a = row4[d4], u = us4[d4];
                    part += a.x * u.x + a.y * u.y + a.z * u.z + a.w * u.w;
                }
                part = warp_sum(part);
                if (lane == 0) sl[s] = part;
            }
            __syncthreads();
            if (wrp == 0) {
                float mx = -1e30f;
                for (int i = lane; i < Ss; i += 32) mx = fmaxf(mx, sl[i]);
                mx = warp_max(mx);
                float sm = 0.f;
                for (int i = lane; i < Ss; i += 32) { float e = __expf(sl[i] - mx); sl[i] = e; sm += e; }
                sm = warp_sum(sm);
                if (lane == 0) red = 1.f / sm;
            }
            __syncthreads();
            const float inv = red;
            float a = 0.f;
#pragma unroll 8
            for (int s = 0; s < Ss; s++) a += sl[s] * cb[(size_t)s * Dd + d];
            g_c[b * Dd + d] = a * inv;
        }
        grid_sync(gen);

        // ---- G(t+1): comb(c(t+1)) [48 jobs] + write(t) [64 jobs if t>=0] ----
        if (t + 1 < Tt) {
            int njobs = (t >= 0) ? 112 : 48;
            for (int j = bid; j < njobs; j += NB) {
                if (j < 48) do_comb(j / 12, j % 12, Wrc, Wra, Wcq, sh);
                else { int r = j - 48; do_write(t, r >> 3, r & 7, Wwc, sh); }
            }
        } else {
            // final write(Tt-1)
            for (int j = bid; j < 64; j += NB) do_write(Tt - 1, j >> 3, j & 7, Wwc, sh);
        }
        grid_sync(gen);
    }

    // ===== final output: reduce write(11) partials (fpB, Tt-1 odd) =====
    {
        float v = 0.f;
#pragma unroll
        for (int z = 0; z < ZW; z++) v += g_fpB[(size_t)z * (Bb * D2) + bid * D2 + tid];
        out[bid * Dd + tid] = v + bwc[tid];
    }
}

// ---------------- host ----------------
extern "C" void kernel_launch(void* const* d_in, const int* in_sizes, int n_in,
                              void* d_out, int out_size)
{
    const float* ctx  = (const float*)d_in[0];
    const float* q    = (const float*)d_in[1];
    const float* kten = (const float*)d_in[2];
    const float* mem0 = (const float*)d_in[3];
    const float* ctrl0= (const float*)d_in[4];
    const float* Wp   = (const float*)d_in[5];
    const float* bp   = (const float*)d_in[6];
    const float* Wcq  = (const float*)d_in[7];
    const float* bcq  = (const float*)d_in[8];
    const float* Wca  = (const float*)d_in[9];
    const float* Wrm  = (const float*)d_in[11];
    const float* brm  = (const float*)d_in[12];
    const float* Wrc  = (const float*)d_in[13];
    const float* Wra  = (const float*)d_in[15];
    const float* Wwc  = (const float*)d_in[17];
    const float* bwc  = (const float*)d_in[18];
    float* out = (float*)d_out;

    mac_mega<<<NB, NTH>>>(ctx, q, kten, mem0, ctrl0, Wp, bp, Wcq, bcq, Wca,
                          Wrm, brm, Wrc, Wra, Wwc, bwc, out);

    (void)in_sizes; (void)n_in; (void)out_size;
}

// round 13
// speedup vs baseline: 1.9493x; 1.9493x over previous
#include <cuda_runtime.h>
#include <math.h>

#define Bb 128
#define Ss 128
#define Nn 196
#define Dd 512
#define D2 1024
#define Tt 12
#define N3 1536

#define NB 128
#define NTH 512

#define ZP 8       // p GEMM split-K (K=128 chunks)
#define ZB 4       // Wrm@Wwc split-K
#define Z2 4       // P2 split-K
#define ZC 4       // comb split-K
#define ZW 8       // write split-K

// ---------------- device scratch ----------------
__device__ float g_pp   [ZP * Bb * Tt * Dd];
__device__ float g_pfull[Bb * Tt * Dd];
__device__ float g_P2p  [Z2 * Bb * Tt * Dd];
__device__ float g_cbp  [ZC * Bb * N3];
__device__ float g_fpA  [ZW * Bb * D2];
__device__ float g_fpB  [ZW * Bb * D2];
__device__ float g_BcP  [ZB * Dd * D2];
__device__ float g_BcF  [Dd * D2];
__device__ float g_bp2  [Tt * Dd];
__device__ float g_c    [Bb * Dd];
__device__ float g_m0   [Bb * Dd];
__device__ float g_mf   [Bb * Dd];
__device__ float g_r    [Bb * Dd];
__device__ float g_bias2[Dd];
__device__ float g_mmrow[Dd];

__device__ int          g_bar_count = 0;
__device__ volatile int g_bar_gen   = 0;

// ---------------- helpers ----------------
__device__ __forceinline__ float warp_sum(float v) {
#pragma unroll
    for (int o = 16; o; o >>= 1) v += __shfl_xor_sync(0xffffffffu, v, o);
    return v;
}
__device__ __forceinline__ float warp_max(float v) {
#pragma unroll
    for (int o = 16; o; o >>= 1) v = fmaxf(v, __shfl_xor_sync(0xffffffffu, v, o));
    return v;
}

// grid barrier: all NB blocks co-resident by construction
__device__ __forceinline__ void grid_sync(int& gen) {
    __syncthreads();
    if (threadIdx.x == 0) {
        __threadfence();
        if (atomicAdd(&g_bar_count, 1) == NB - 1) {
            g_bar_count = 0;
            __threadfence();
            g_bar_gen = gen + 1;
        } else {
            while ((int)(g_bar_gen - gen) <= 0) { }
        }
        __threadfence();
    }
    __syncthreads();
    gen++;
}

// ---------------- GEMM tile: C[128,128] = A[128,klen] * B^T ------------------
// B(n,k) = B[n*ldbN + k*ldbK] (+optional per-k scale ks on NN path).
// 512 threads: warp ty -> m rows ty*8..+7, lane tx -> n cols tx*4..+3.
// 32 scalar fp32 accumulators per thread (no spills).
__device__ void gemm_tile(const float* __restrict__ A, int lda,
                          const float* __restrict__ B, int ldbN, int ldbK,
                          const float* __restrict__ ks,
                          float* __restrict__ C, int ldc, int klen,
                          float* __restrict__ sh)
{
    float* As = sh;              // [16][132]
    float* Bs = sh + 16 * 132;   // [16][132]
    const int tid = threadIdx.x;
    const int ty = tid >> 5, tx = tid & 31;
    const int aRow = tid >> 2, aK4 = (tid & 3) << 2;   // A / B-NT loader map
    const int bK = tid >> 5, bN4 = (tid & 31) << 2;    // B-NN loader map
    const bool nt = (ldbK == 1);

    float acc[8][4];
#pragma unroll
    for (int i = 0; i < 8; i++)
#pragma unroll
        for (int j = 0; j < 4; j++) acc[i][j] = 0.f;

    float4 ra, rb;
    ra = *(const float4*)(A + (size_t)aRow * lda + aK4);
    if (nt) {
        rb = *(const float4*)(B + (size_t)aRow * ldbN + aK4);
    } else {
        rb = *(const float4*)(B + (size_t)bK * ldbK + bN4);
        if (ks) { float s = ks[bK]; rb.x *= s; rb.y *= s; rb.z *= s; rb.w *= s; }
    }

    for (int k0 = 0; k0 < klen; k0 += 16) {
        As[(aK4 + 0) * 132 + aRow] = ra.x;
        As[(aK4 + 1) * 132 + aRow] = ra.y;
        As[(aK4 + 2) * 132 + aRow] = ra.z;
        As[(aK4 + 3) * 132 + aRow] = ra.w;
        if (nt) {
            Bs[(aK4 + 0) * 132 + aRow] = rb.x;
            Bs[(aK4 + 1) * 132 + aRow] = rb.y;
            Bs[(aK4 + 2) * 132 + aRow] = rb.z;
            Bs[(aK4 + 3) * 132 + aRow] = rb.w;
        } else {
            *(float4*)(Bs + bK * 132 + bN4) = rb;
        }
        __syncthreads();

        if (k0 + 16 < klen) {
            int kn = k0 + 16;
            ra = *(const float4*)(A + (size_t)aRow * lda + kn + aK4);
            if (nt) {
                rb = *(const float4*)(B + (size_t)aRow * ldbN + kn + aK4);
            } else {
                rb = *(const float4*)(B + (size_t)(kn + bK) * ldbK + bN4);
                if (ks) { float s = ks[kn + bK]; rb.x *= s; rb.y *= s; rb.z *= s; rb.w *= s; }
            }
        }

#pragma unroll
        for (int kk = 0; kk < 16; kk++) {
            float4 a0 = *(const float4*)(As + kk * 132 + ty * 8);
            float4 a1 = *(const float4*)(As + kk * 132 + ty * 8 + 4);
            float4 b  = *(const float4*)(Bs + kk * 132 + tx * 4);
            float av[8] = {a0.x, a0.y, a0.z, a0.w, a1.x, a1.y, a1.z, a1.w};
            float bv[4] = {b.x, b.y, b.z, b.w};
#pragma unroll
            for (int i = 0; i < 8; i++)
#pragma unroll
                for (int j = 0; j < 4; j++) acc[i][j] += av[i] * bv[j];
        }
        __syncthreads();
    }

#pragma unroll
    for (int i = 0; i < 8; i++) {
        int m = ty * 8 + i;
        *(float4*)(C + (size_t)m * ldc + tx * 4) =
            make_float4(acc[i][0], acc[i][1], acc[i][2], acc[i][3]);
    }
}

// comb job: z in [0,ZC), nI in [0,12): c @ [Wra*Wrc^T ; Wcq1]^T chunk
__device__ __forceinline__ void do_comb(int z, int nI,
                                        const float* __restrict__ Wrc,
                                        const float* __restrict__ Wra,
                                        const float* __restrict__ Wcq,
                                        float* sh)
{
    int kbeg = z * 128, bn = nI * 128;
    if (bn < D2) {
        gemm_tile(g_c + kbeg, Dd,
                  Wrc + (size_t)kbeg * D2 + bn, 1, D2, Wra + kbeg,
                  g_cbp + (size_t)z * (Bb * N3) + bn, N3, 128, sh);
    } else {
        gemm_tile(g_c + kbeg, Dd,
                  Wcq + (size_t)(bn - D2) * D2 + kbeg, D2, 1, nullptr,
                  g_cbp + (size_t)z * (Bb * N3) + bn, N3, 128, sh);
    }
}

// write job: z in [0,ZW), nI in [0,8): concat(r, m_tw) @ [Wwc ; Wrm@Wwc]^T
__device__ __forceinline__ void do_write(int tw, int z, int nI,
                                         const float* __restrict__ Wwc,
                                         float* sh)
{
    int kbeg = z * 128, bn = nI * 128;
    const float* A = (kbeg < Dd) ? (g_r + kbeg)
                                 : ((tw == 0 ? g_m0 : g_mf) + (kbeg - Dd));
    const float* Bp = (bn < Dd) ? (Wwc + (size_t)bn * D2 + kbeg)
                                : (g_BcF + (size_t)(bn - Dd) * D2 + kbeg);
    float* fp = (tw & 1) ? g_fpB : g_fpA;
    gemm_tile(A, Dd, Bp, D2, 1, nullptr,
              fp + (size_t)z * (Bb * D2) + bn, D2, 128, sh);
}

// ---------------- persistent mega-kernel ----------------
__global__ void __launch_bounds__(NTH, 1) mac_mega(
    const float* __restrict__ ctx, const float* __restrict__ q,
    const float* __restrict__ kten, const float* __restrict__ mem0,
    const float* __restrict__ ctrl0, const float* __restrict__ Wp,
    const float* __restrict__ bp, const float* __restrict__ Wcq,
    const float* __restrict__ bcq, const float* __restrict__ Wca,
    const float* __restrict__ Wrm, const float* __restrict__ brm,
    const float* __restrict__ Wrc, const float* __restrict__ Wra,
    const float* __restrict__ Wwc, const float* __restrict__ bwc,
    float* __restrict__ out)
{
    __shared__ __align__(16) float sh[2 * 16 * 132];
    __shared__ __align__(16) float us[Dd];
    __shared__ float sl[Ss];
    __shared__ float rw0[256];
    __shared__ float rw1[256];
    __shared__ float red;

    const int bid = blockIdx.x;
    const int tid = threadIdx.x;
    const int lane = tid & 31, wrp = tid >> 5;
    int gen = g_bar_gen;

    // ===== S1: init + small dots + p GEMM (384 jobs) + Wrm@Wwc (128 jobs) =====
    {
        int i = bid * NTH + tid;
        g_c[i]  = ctrl0[i & (Dd - 1)];
        g_m0[i] = mem0[i & (Dd - 1)];
    }
    for (int job = bid * 16 + wrp; job < 512 + Tt * Dd; job += NB * 16) {
        if (job < 512) {
            int d = job;
            const float* row = Wrm + (size_t)d * Dd;
            float s1 = 0.f, s2 = 0.f;
            for (int j = lane; j < Dd; j += 32) { float x = row[j]; s1 += x * bwc[j]; s2 += x * mem0[j]; }
            s1 = warp_sum(s1); s2 = warp_sum(s2);
            if (lane == 0) { g_bias2[d] = brm[d] + s1; g_mmrow[d] = brm[d] + s2; }
        } else {
            int idx = job - 512; int t = idx >> 9, d = idx & 511;
            float s = 0.f;
            for (int j = lane; j < Dd; j += 32) s += bp[t * Dd + j] * Wcq[(size_t)d * D2 + Dd + j];
            s = warp_sum(s);
            if (lane == 0) g_bp2[t * Dd + d] = s;
        }
    }
    for (int j = bid; j < 384 + 128; j += NB) {
        if (j < 384) {
            int z = j / 48, nI = j % 48;
            gemm_tile(q + z * 128, D2,
                      Wp + (size_t)(nI * 128) * D2 + z * 128, D2, 1, nullptr,
                      g_pp + (size_t)z * (Bb * Tt * Dd) + nI * 128, Tt * Dd, 128, sh);
        } else {
            int r = j - 384; int z = r >> 5, mI = (r >> 3) & 3, nI = r & 7;
            gemm_tile(Wrm + (size_t)(mI * 128) * Dd + z * 128, Dd,
                      Wwc + (size_t)(z * 128) * D2 + nI * 128, 1, D2, nullptr,
                      g_BcP + (size_t)z * (Dd * D2) + (size_t)(mI * 128) * D2 + nI * 128,
                      D2, 128, sh);
        }
    }
    grid_sync(gen);

    // ===== S1.5: reduce p and BcBot partials =====
    {
        const int tot = Bb * Tt * Dd;
        for (int i = bid * NTH + tid; i < tot; i += NB * NTH) {
            float v = 0.f;
#pragma unroll
            for (int z = 0; z < ZP; z++) v += g_pp[(size_t)z * tot + i];
            g_pfull[i] = v;
        }
        const int tot2 = Dd * D2;
        for (int i = bid * NTH + tid; i < tot2; i += NB * NTH) {
            float v = 0.f;
#pragma unroll
            for (int z = 0; z < ZB; z++) v += g_BcP[(size_t)z * tot2 + i];
            g_BcF[i] = v;
        }
    }
    grid_sync(gen);

    // ===== S2: P2 GEMM (192 jobs) + comb(c(-1)) u-half only (16 jobs) =====
    for (int j = bid; j < 192 + 16; j += NB) {
        if (j < 192) {
            int z = j / 48, r = j % 48, mI = r >> 2, nI = r & 3;
            gemm_tile(g_pfull + (size_t)(mI * 128) * Dd + z * 128, Dd,
                      Wcq + (size_t)(nI * 128) * D2 + Dd + z * 128, D2, 1, nullptr,
                      g_P2p + (size_t)z * (Bb * Tt * Dd) + (size_t)(mI * 128) * Dd + nI * 128,
                      Dd, 128, sh);
        } else {
            int r = j - 192;
            do_comb(r >> 2, 8 + (r & 3), Wrc, Wra, Wcq, sh);
        }
    }
    grid_sync(gen);

    // ===== main loop: A-phase (attn_k(t) + attn_ctx(t+1)) | G-phase =====
    for (int t = -1; t < Tt; t++) {
        const int b = bid, d = tid;
        if (t >= 0) {
            // ---- attn_k(t) (+ reduce mm(t), m(t)) ----
            float w2a = 0.f, w2b = 0.f;
#pragma unroll
            for (int z = 0; z < ZC; z++) {
                w2a += g_cbp[(size_t)z * (Bb * N3) + b * N3 + d];
                w2b += g_cbp[(size_t)z * (Bb * N3) + b * N3 + Dd + d];
            }
            float mmv;
            if (t == 0) {
                mmv = g_mmrow[d];
            } else {
                const float* fp = ((t - 1) & 1) ? g_fpB : g_fpA;
                float s1 = 0.f, mval = 0.f;
#pragma unroll
                for (int z = 0; z < ZW; z++) {
                    s1   += fp[(size_t)z * (Bb * D2) + b * D2 + Dd + d];
                    mval += fp[(size_t)z * (Bb * D2) + b * D2 + d];
                }
                mmv = s1 + g_bias2[d];
                g_mf[b * Dd + d] = mval + bwc[d];
            }
            us[d] = w2a * mmv + w2b;
            __syncthreads();

            const float* kb = kten + (size_t)b * Dd * Nn;
            {
                int half = tid >> 8, n = tid & 255;
                if (n < Nn) {
                    float acc = 0.f;
                    int j0 = half * 256;
#pragma unroll 8
                    for (int j2 = j0; j2 < j0 + 256; j2++) acc += us[j2] * kb[(size_t)j2 * Nn + n];
                    (half ? rw1 : rw0)[n] = acc;
                }
            }
            __syncthreads();
            if (tid < Nn) rw0[tid] += rw1[tid];
            __syncthreads();
            if (wrp == 0) {
                float mx = -1e30f;
                for (int i = lane; i < Nn; i += 32) mx = fmaxf(mx, rw0[i]);
                mx = warp_max(mx);
                float sm = 0.f;
                for (int i = lane; i < Nn; i += 32) { float e = __expf(rw0[i] - mx); rw0[i] = e; sm += e; }
                sm = warp_sum(sm);
                if (lane == 0) red = 1.f / sm;
            }
            __syncthreads();
            const float inv = red;
            // pass 2: 2 rows per warp, independent accumulators for MLP
            for (int d0 = wrp * 2; d0 < Dd; d0 += 32) {
                const float* r0p = kb + (size_t)d0 * Nn;
                const float* r1p = r0p + Nn;
                float p0 = 0.f, p1 = 0.f;
#pragma unroll
                for (int n = lane; n < 224; n += 32) {
                    if (n < Nn) {
                        float w = rw0[n];
                        p0 += w * r0p[n];
                        p1 += w * r1p[n];
                    }
                }
                p0 = warp_sum(p0); p1 = warp_sum(p1);
                if (lane == 0) {
                    g_r[b * Dd + d0]     = p0 * inv;
                    g_r[b * Dd + d0 + 1] = p1 * inv;
                }
            }
            __syncthreads();
        }

        if (t + 1 < Tt) {
            // ---- attn_ctx(t+1) ----
            const int tc = t + 1;
            float v = 0.f;
#pragma unroll
            for (int z = 0; z < ZC; z++) v += g_cbp[(size_t)z * (Bb * N3) + b * N3 + D2 + d];
            float v2 = 0.f;
#pragma unroll
            for (int z = 0; z < Z2; z++) v2 += g_P2p[(size_t)z * (Bb * Tt * Dd) + (b * Tt + tc) * Dd + d];
            v += v2 + bcq[d] + g_bp2[tc * Dd + d];
            us[d] = v * Wca[d];
            __syncthreads();

            const float* cb = ctx + (size_t)b * Ss * Dd;
            const float4* us4 = (const float4*)us;
            for (int s = wrp; s < Ss; s += 16) {
                const float4* row4 = (const float4*)(cb + (size_t)s * Dd);
                float part = 0.f;
#pragma unroll
                for (int d4 = lane; d4 < Dd / 4; d4 += 32) {
                    float4 a = row4[d4], u = us4[d4];
                    part += a.x * u.x + a.y * u.y + a.z * u.z + a.w * u.w;
                }
                part = warp_sum(part);
                if (lane == 0) sl[s] = part;
            }
            __syncthreads();
            if (wrp == 0) {
                float mx = -1e30f;
                for (int i = lane; i < Ss; i += 32) mx = fmaxf(mx, sl[i]);
                mx = warp_max(mx);
                float sm = 0.f;
                for (int i = lane; i < Ss; i += 32) { float e = __expf(sl[i] - mx); sl[i] = e; sm += e; }
                sm = warp_sum(sm);
                if (lane == 0) red = 1.f / sm;
            }
            __syncthreads();
            const float inv = red;
            float a = 0.f;
#pragma unroll 8
            for (int s = 0; s < Ss; s++) a += sl[s] * cb[(size_t)s * Dd + d];
            g_c[b * Dd + d] = a * inv;
        }
        grid_sync(gen);

        // ---- G(t+1): comb(c(t+1)) [48 jobs] + write(t) [64 jobs if t>=0] ----
        if (t + 1 < Tt) {
            int njobs = (t >= 0) ? 112 : 48;
            for (int j = bid; j < njobs; j += NB) {
                if (j < 48) do_comb(j / 12, j % 12, Wrc, Wra, Wcq, sh);
                else { int r = j - 48; do_write(t, r >> 3, r & 7, Wwc, sh); }
            }
        } else {
            // final write(Tt-1): only the m-half (nI 0..3) is needed for out
            for (int j = bid; j < 32; j += NB) do_write(Tt - 1, j >> 2, j & 3, Wwc, sh);
        }
        grid_sync(gen);
    }

    // ===== final output: reduce write(11) partials (fpB, Tt-1 odd) =====
    {
        float v = 0.f;
#pragma unroll
        for (int z = 0; z < ZW; z++) v += g_fpB[(size_t)z * (Bb * D2) + bid * D2 + tid];
        out[bid * Dd + tid] = v + bwc[tid];
    }
}

// ---------------- host ----------------
extern "C" void kernel_launch(void* const* d_in, const int* in_sizes, int n_in,
                              void* d_out, int out_size)
{
    const float* ctx  = (const float*)d_in[0];
    const float* q    = (const float*)d_in[1];
    const float* kten = (const float*)d_in[2];
    const float* mem0 = (const float*)d_in[3];
    const float* ctrl0= (const float*)d_in[4];
    const float* Wp   = (const float*)d_in[5];
    const float* bp   = (const float*)d_in[6];
    const float* Wcq  = (const float*)d_in[7];
    const float* bcq  = (const float*)d_in[8];
    const float* Wca  = (const float*)d_in[9];
    const float* Wrm  = (const float*)d_in[11];
    const float* brm  = (const float*)d_in[12];
    const float* Wrc  = (const float*)d_in[13];
    const float* Wra  = (const float*)d_in[15];
    const float* Wwc  = (const float*)d_in[17];
    const float* bwc  = (const float*)d_in[18];
    float* out = (float*)d_out;

    mac_mega<<<NB, NTH>>>(ctx, q, kten, mem0, ctrl0, Wp, bp, Wcq, bcq, Wca,
                          Wrm, brm, Wrc, Wra, Wwc, bwc, out);

    (void)in_sizes; (void)n_in; (void)out_size;
}

// round 16
// speedup vs baseline: 2.2130x; 1.1353x over previous
#include <cuda_runtime.h>
#include <cuda_bf16.h>
#include <stdint.h>
#include <math.h>

#define Bb 128
#define Ss 128
#define Nn 196
#define Dd 512
#define D2 1024
#define Tt 12
#define N3 1536

#define NB 128
#define NTH 512

#define ZP 8       // p GEMM split-K (K=128 chunks)
#define ZB 4       // Wrm@Wwc split-K
#define Z2 4       // P2 split-K
#define ZC 4       // comb split-K
#define ZW 8       // write split-K

// bf16 tile geometry: 128 rows x 16 k, rows padded to 24 bf16 (48B)
#define TROW 48
#define TSZ  6144          // 128*48
#define BUFSZ (4*TSZ)      // Ah, Al, Bh, Bl

// dynamic smem layout
#define SM_TILES   0                    // 2 buffers * 24576 = 49152
#define SM_US      49152                // 512 f
#define SM_SL      51200                // 128 f
#define SM_RW0     51712                // 256 f
#define SM_RW1     52736                // 256 f
#define SM_RED     53760
#define SMEM_TOTAL 53824

// ---------------- device scratch ----------------
__device__ float g_pp   [ZP * Bb * Tt * Dd];
__device__ float g_pfull[Bb * Tt * Dd];
__device__ float g_P2p  [Z2 * Bb * Tt * Dd];
__device__ float g_cbp  [ZC * Bb * N3];
__device__ float g_fpA  [ZW * Bb * D2];
__device__ float g_fpB  [ZW * Bb * D2];
__device__ float g_BcP  [ZB * Dd * D2];
__device__ float g_BcF  [Dd * D2];
__device__ float g_bp2  [Tt * Dd];
__device__ float g_c    [Bb * Dd];
__device__ float g_m0   [Bb * Dd];
__device__ float g_mf   [Bb * Dd];
__device__ float g_r    [Bb * Dd];
__device__ float g_bias2[Dd];
__device__ float g_mmrow[Dd];

__device__ int          g_bar_count = 0;
__device__ volatile int g_bar_gen   = 0;

// ---------------- helpers ----------------
__device__ __forceinline__ float warp_sum(float v) {
#pragma unroll
    for (int o = 16; o; o >>= 1) v += __shfl_xor_sync(0xffffffffu, v, o);
    return v;
}
__device__ __forceinline__ float warp_max(float v) {
#pragma unroll
    for (int o = 16; o; o >>= 1) v = fmaxf(v, __shfl_xor_sync(0xffffffffu, v, o));
    return v;
}
__device__ __forceinline__ uint32_t smem_u32(const void* p) {
    uint32_t a;
    asm("{ .reg .u64 t; cvta.to.shared.u64 t, %1; cvt.u32.u64 %0, t; }" : "=r"(a) : "l"(p));
    return a;
}

__device__ __forceinline__ void grid_sync(int& gen) {
    __syncthreads();
    if (threadIdx.x == 0) {
        __threadfence();
        if (atomicAdd(&g_bar_count, 1) == NB - 1) {
            g_bar_count = 0;
            __threadfence();
            g_bar_gen = gen + 1;
        } else {
            while ((int)(g_bar_gen - gen) <= 0) { }
        }
        __threadfence();
    }
    __syncthreads();
    gen++;
}

// ---------------- mma building blocks ----------------
__device__ __forceinline__ void ldsm4(uint32_t r[4], uint32_t addr) {
    asm volatile("ldmatrix.sync.aligned.m8n8.x4.shared.b16 {%0,%1,%2,%3}, [%4];"
                 : "=r"(r[0]), "=r"(r[1]), "=r"(r[2]), "=r"(r[3]) : "r"(addr));
}
__device__ __forceinline__ void mma_bf16(float c[4], const uint32_t a[4],
                                         uint32_t b0, uint32_t b1) {
    asm volatile("mma.sync.aligned.m16n8k16.row.col.f32.bf16.bf16.f32 "
                 "{%0,%1,%2,%3}, {%4,%5,%6,%7}, {%8,%9}, {%0,%1,%2,%3};"
                 : "+f"(c[0]), "+f"(c[1]), "+f"(c[2]), "+f"(c[3])
                 : "r"(a[0]), "r"(a[1]), "r"(a[2]), "r"(a[3]), "r"(b0), "r"(b1));
}

// split fp32 -> (hi, lo) bf16 and store 4 consecutive k into hi/lo tiles
__device__ __forceinline__ void st_tile(char* hi, char* lo, int row, int k4, float4 v) {
    __nv_bfloat16 h0 = __float2bfloat16(v.x);
    __nv_bfloat16 h1 = __float2bfloat16(v.y);
    __nv_bfloat16 h2 = __float2bfloat16(v.z);
    __nv_bfloat16 h3 = __float2bfloat16(v.w);
    __nv_bfloat16 l0 = __float2bfloat16(v.x - __bfloat162float(h0));
    __nv_bfloat16 l1 = __float2bfloat16(v.y - __bfloat162float(h1));
    __nv_bfloat16 l2 = __float2bfloat16(v.z - __bfloat162float(h2));
    __nv_bfloat16 l3 = __float2bfloat16(v.w - __bfloat162float(h3));
    int off = row * TROW + k4 * 2;
    *(__nv_bfloat162*)(hi + off)     = __halves2bfloat162(h0, h1);
    *(__nv_bfloat162*)(hi + off + 4) = __halves2bfloat162(h2, h3);
    *(__nv_bfloat162*)(lo + off)     = __halves2bfloat162(l0, l1);
    *(__nv_bfloat162*)(lo + off + 4) = __halves2bfloat162(l2, l3);
}

// ---------------- GEMM tile: C[128,128] = A[128,klen] * B^T, split-bf16 HMMA --
// B(n,k) = B[n*ldbN + k*ldbK] (+optional per-k scale ks on NN path).
// 512 threads; warp w: rows (w&3)*32..+31, cols (w>>2)*32..+31.
__device__ void gemm_tile(const float* __restrict__ A, int lda,
                          const float* __restrict__ B, int ldbN, int ldbK,
                          const float* __restrict__ ks,
                          float* __restrict__ C, int ldc, int klen,
                          char* sh)
{
    const int tid = threadIdx.x;
    const int lane = tid & 31, w = tid >> 5;
    const int mw = (w & 3) * 32, nw = (w >> 2) * 32;
    const bool nt = (ldbK == 1);
    const int aM = tid >> 2, aK4 = (tid & 3) << 2;     // A & B-NT loader
    const int bN = tid & 127, bKq = (tid >> 7) << 2;   // B-NN loader
    const uint32_t shb = smem_u32(sh);

    float acc[2][4][4];
#pragma unroll
    for (int i = 0; i < 2; i++)
#pragma unroll
        for (int j = 0; j < 4; j++)
#pragma unroll
            for (int q = 0; q < 4; q++) acc[i][j][q] = 0.f;

    // ldmatrix per-lane offsets (within one buffer)
    const uint32_t aoff = (uint32_t)((lane & 15) * TROW + (lane >> 4) * 16);
    const uint32_t boff = (uint32_t)((((lane >> 4) << 3) + (lane & 7)) * TROW
                                     + ((lane >> 3) & 1) * 16);

    const int nch = klen >> 4;
    for (int c = 0; c < nch; c++) {
        const int k0 = c << 4;
        char* base = sh + (c & 1) * BUFSZ;
        // stage: global fp32 -> split bf16 smem
        {
            float4 ra = *(const float4*)(A + (size_t)aM * lda + k0 + aK4);
            st_tile(base, base + TSZ, aM, aK4, ra);
            float4 rb;
            if (nt) {
                rb = *(const float4*)(B + (size_t)aM * ldbN + k0 + aK4);
                st_tile(base + 2 * TSZ, base + 3 * TSZ, aM, aK4, rb);
            } else {
                rb.x = B[(size_t)(k0 + bKq + 0) * ldbK + bN];
                rb.y = B[(size_t)(k0 + bKq + 1) * ldbK + bN];
                rb.z = B[(size_t)(k0 + bKq + 2) * ldbK + bN];
                rb.w = B[(size_t)(k0 + bKq + 3) * ldbK + bN];
                if (ks) {
                    rb.x *= ks[k0 + bKq + 0];
                    rb.y *= ks[k0 + bKq + 1];
                    rb.z *= ks[k0 + bKq + 2];
                    rb.w *= ks[k0 + bKq + 3];
                }
                st_tile(base + 2 * TSZ, base + 3 * TSZ, bN, bKq, rb);
            }
        }
        __syncthreads();

        const uint32_t bb = shb + (uint32_t)((c & 1) * BUFSZ);
        uint32_t ah[2][4], alr[2][4], bh[2][4], blr[2][4];
        ldsm4(ah[0],  bb + (uint32_t)(mw * TROW) + aoff);
        ldsm4(ah[1],  bb + (uint32_t)((mw + 16) * TROW) + aoff);
        ldsm4(alr[0], bb + TSZ + (uint32_t)(mw * TROW) + aoff);
        ldsm4(alr[1], bb + TSZ + (uint32_t)((mw + 16) * TROW) + aoff);
        ldsm4(bh[0],  bb + 2 * TSZ + (uint32_t)(nw * TROW) + boff);
        ldsm4(bh[1],  bb + 2 * TSZ + (uint32_t)((nw + 16) * TROW) + boff);
        ldsm4(blr[0], bb + 3 * TSZ + (uint32_t)(nw * TROW) + boff);
        ldsm4(blr[1], bb + 3 * TSZ + (uint32_t)((nw + 16) * TROW) + boff);

        // hh pass
#pragma unroll
        for (int mt = 0; mt < 2; mt++)
#pragma unroll
            for (int ns = 0; ns < 4; ns++)
                mma_bf16(acc[mt][ns], ah[mt],
                         bh[ns >> 1][(ns & 1) * 2], bh[ns >> 1][(ns & 1) * 2 + 1]);
        // hl pass
#pragma unroll
        for (int mt = 0; mt < 2; mt++)
#pragma unroll
            for (int ns = 0; ns < 4; ns++)
                mma_bf16(acc[mt][ns], ah[mt],
                         blr[ns >> 1][(ns & 1) * 2], blr[ns >> 1][(ns & 1) * 2 + 1]);
        // lh pass
#pragma unroll
        for (int mt = 0; mt < 2; mt++)
#pragma unroll
            for (int ns = 0; ns < 4; ns++)
                mma_bf16(acc[mt][ns], alr[mt],
                         bh[ns >> 1][(ns & 1) * 2], bh[ns >> 1][(ns & 1) * 2 + 1]);
        __syncthreads();
    }

    // epilogue: c-frag -> C
#pragma unroll
    for (int mt = 0; mt < 2; mt++)
#pragma unroll
        for (int ns = 0; ns < 4; ns++) {
            int r0 = mw + mt * 16 + (lane >> 2);
            int col = nw + ns * 8 + (lane & 3) * 2;
            *(float2*)(C + (size_t)r0 * ldc + col) =
                make_float2(acc[mt][ns][0], acc[mt][ns][1]);
            *(float2*)(C + (size_t)(r0 + 8) * ldc + col) =
                make_float2(acc[mt][ns][2], acc[mt][ns][3]);
        }
}

// comb job: z in [0,ZC), nI in [0,12): c @ [Wra*Wrc^T ; Wcq1]^T chunk
__device__ __forceinline__ void do_comb(int z, int nI,
                                        const float* __restrict__ Wrc,
                                        const float* __restrict__ Wra,
                                        const float* __restrict__ Wcq,
                                        char* sh)
{
    int kbeg = z * 128, bn = nI * 128;
    if (bn < D2) {
        gemm_tile(g_c + kbeg, Dd,
                  Wrc + (size_t)kbeg * D2 + bn, 1, D2, Wra + kbeg,
                  g_cbp + (size_t)z * (Bb * N3) + bn, N3, 128, sh);
    } else {
        gemm_tile(g_c + kbeg, Dd,
                  Wcq + (size_t)(bn - D2) * D2 + kbeg, D2, 1, nullptr,
                  g_cbp + (size_t)z * (Bb * N3) + bn, N3, 128, sh);
    }
}

// write job: z in [0,ZW), nI in [0,8): concat(r, m_tw) @ [Wwc ; Wrm@Wwc]^T
__device__ __forceinline__ void do_write(int tw, int z, int nI,
                                         const float* __restrict__ Wwc,
                                         char* sh)
{
    int kbeg = z * 128, bn = nI * 128;
    const float* A = (kbeg < Dd) ? (g_r + kbeg)
                                 : ((tw == 0 ? g_m0 : g_mf) + (kbeg - Dd));
    const float* Bp = (bn < Dd) ? (Wwc + (size_t)bn * D2 + kbeg)
                                : (g_BcF + (size_t)(bn - Dd) * D2 + kbeg);
    float* fp = (tw & 1) ? g_fpB : g_fpA;
    gemm_tile(A, Dd, Bp, D2, 1, nullptr,
              fp + (size_t)z * (Bb * D2) + bn, D2, 128, sh);
}

// ---------------- persistent mega-kernel ----------------
__global__ void __launch_bounds__(NTH, 1) mac_mega(
    const float* __restrict__ ctx, const float* __restrict__ q,
    const float* __restrict__ kten, const float* __restrict__ mem0,
    const float* __restrict__ ctrl0, const float* __restrict__ Wp,
    const float* __restrict__ bp, const float* __restrict__ Wcq,
    const float* __restrict__ bcq, const float* __restrict__ Wca,
    const float* __restrict__ Wrm, const float* __restrict__ brm,
    const float* __restrict__ Wrc, const float* __restrict__ Wra,
    const float* __restrict__ Wwc, const float* __restrict__ bwc,
    float* __restrict__ out)
{
    extern __shared__ char smem[];
    char*  sht = smem + SM_TILES;
    float* us  = (float*)(smem + SM_US);
    float* sl  = (float*)(smem + SM_SL);
    float* rw0 = (float*)(smem + SM_RW0);
    float* rw1 = (float*)(smem + SM_RW1);
    float* red = (float*)(smem + SM_RED);

    const int bid = blockIdx.x;
    const int tid = threadIdx.x;
    const int lane = tid & 31, wrp = tid >> 5;
    int gen = g_bar_gen;

    // ===== S1: init + small dots + p GEMM (384 jobs) + Wrm@Wwc (128 jobs) =====
    {
        int i = bid * NTH + tid;
        g_c[i]  = ctrl0[i & (Dd - 1)];
        g_m0[i] = mem0[i & (Dd - 1)];
    }
    for (int job = bid * 16 + wrp; job < 512 + Tt * Dd; job += NB * 16) {
        if (job < 512) {
            int d = job;
            const float* row = Wrm + (size_t)d * Dd;
            float s1 = 0.f, s2 = 0.f;
            for (int j = lane; j < Dd; j += 32) { float x = row[j]; s1 += x * bwc[j]; s2 += x * mem0[j]; }
            s1 = warp_sum(s1); s2 = warp_sum(s2);
            if (lane == 0) { g_bias2[d] = brm[d] + s1; g_mmrow[d] = brm[d] + s2; }
        } else {
            int idx = job - 512; int t = idx >> 9, d = idx & 511;
            float s = 0.f;
            for (int j = lane; j < Dd; j += 32) s += bp[t * Dd + j] * Wcq[(size_t)d * D2 + Dd + j];
            s = warp_sum(s);
            if (lane == 0) g_bp2[t * Dd + d] = s;
        }
    }
    __syncthreads();
    for (int j = bid; j < 384 + 128; j += NB) {
        if (j < 384) {
            int z = j / 48, nI = j % 48;
            gemm_tile(q + z * 128, D2,
                      Wp + (size_t)(nI * 128) * D2 + z * 128, D2, 1, nullptr,
                      g_pp + (size_t)z * (Bb * Tt * Dd) + nI * 128, Tt * Dd, 128, sht);
        } else {
            int r = j - 384; int z = r >> 5, mI = (r >> 3) & 3, nI = r & 7;
            gemm_tile(Wrm + (size_t)(mI * 128) * Dd + z * 128, Dd,
                      Wwc + (size_t)(z * 128) * D2 + nI * 128, 1, D2, nullptr,
                      g_BcP + (size_t)z * (Dd * D2) + (size_t)(mI * 128) * D2 + nI * 128,
                      D2, 128, sht);
        }
    }
    grid_sync(gen);

    // ===== S1.5: reduce p and BcBot partials =====
    {
        const int tot = Bb * Tt * Dd;
        for (int i = bid * NTH + tid; i < tot; i += NB * NTH) {
            float v = 0.f;
#pragma unroll
            for (int z = 0; z < ZP; z++) v += g_pp[(size_t)z * tot + i];
            g_pfull[i] = v;
        }
        const int tot2 = Dd * D2;
        for (int i = bid * NTH + tid; i < tot2; i += NB * NTH) {
            float v = 0.f;
#pragma unroll
            for (int z = 0; z < ZB; z++) v += g_BcP[(size_t)z * tot2 + i];
            g_BcF[i] = v;
        }
    }
    grid_sync(gen);

    // ===== S2: P2 GEMM (192 jobs) + comb(c(-1)) u-half only (16 jobs) =====
    for (int j = bid; j < 192 + 16; j += NB) {
        if (j < 192) {
            int z = j / 48, r = j % 48, mI = r >> 2, nI = r & 3;
            gemm_tile(g_pfull + (size_t)(mI * 128) * Dd + z * 128, Dd,
                      Wcq + (size_t)(nI * 128) * D2 + Dd + z * 128, D2, 1, nullptr,
                      g_P2p + (size_t)z * (Bb * Tt * Dd) + (size_t)(mI * 128) * Dd + nI * 128,
                      Dd, 128, sht);
        } else {
            int r = j - 192;
            do_comb(r >> 2, 8 + (r & 3), Wrc, Wra, Wcq, sht);
        }
    }
    grid_sync(gen);

    // ===== main loop: A-phase (attn_k(t) + attn_ctx(t+1)) | G-phase =====
    for (int t = -1; t < Tt; t++) {
        const int b = bid, d = tid;
        if (t >= 0) {
            // ---- attn_k(t) (+ reduce mm(t), m(t)) ----
            float w2a = 0.f, w2b = 0.f;
#pragma unroll
            for (int z = 0; z < ZC; z++) {
                w2a += g_cbp[(size_t)z * (Bb * N3) + b * N3 + d];
                w2b += g_cbp[(size_t)z * (Bb * N3) + b * N3 + Dd + d];
            }
            float mmv;
            if (t == 0) {
                mmv = g_mmrow[d];
            } else {
                const float* fp = ((t - 1) & 1) ? g_fpB : g_fpA;
                float s1 = 0.f, mval = 0.f;
#pragma unroll
                for (int z = 0; z < ZW; z++) {
                    s1   += fp[(size_t)z * (Bb * D2) + b * D2 + Dd + d];
                    mval += fp[(size_t)z * (Bb * D2) + b * D2 + d];
                }
                mmv = s1 + g_bias2[d];
                g_mf[b * Dd + d] = mval + bwc[d];
            }
            us[d] = w2a * mmv + w2b;
            __syncthreads();

            const float* kb = kten + (size_t)b * Dd * Nn;
            {
                int half = tid >> 8, n = tid & 255;
                if (n < Nn) {
                    float acc = 0.f;
                    int j0 = half * 256;
#pragma unroll 8
                    for (int j2 = j0; j2 < j0 + 256; j2++) acc += us[j2] * kb[(size_t)j2 * Nn + n];
                    (half ? rw1 : rw0)[n] = acc;
                }
            }
            __syncthreads();
            if (tid < Nn) rw0[tid] += rw1[tid];
            __syncthreads();
            if (wrp == 0) {
                float mx = -1e30f;
                for (int i = lane; i < Nn; i += 32) mx = fmaxf(mx, rw0[i]);
                mx = warp_max(mx);
                float sm = 0.f;
                for (int i = lane; i < Nn; i += 32) { float e = __expf(rw0[i] - mx); rw0[i] = e; sm += e; }
                sm = warp_sum(sm);
                if (lane == 0) red[0] = 1.f / sm;
            }
            __syncthreads();
            const float inv = red[0];
            for (int d0 = wrp * 2; d0 < Dd; d0 += 32) {
                const float* r0p = kb + (size_t)d0 * Nn;
                const float* r1p = r0p + Nn;
                float p0 = 0.f, p1 = 0.f;
#pragma unroll
                for (int n = lane; n < 224; n += 32) {
                    if (n < Nn) {
                        float ww = rw0[n];
                        p0 += ww * r0p[n];
                        p1 += ww * r1p[n];
                    }
                }
                p0 = warp_sum(p0); p1 = warp_sum(p1);
                if (lane == 0) {
                    g_r[b * Dd + d0]     = p0 * inv;
                    g_r[b * Dd + d0 + 1] = p1 * inv;
                }
            }
            __syncthreads();
        }

        if (t + 1 < Tt) {
            // ---- attn_ctx(t+1) ----
            const int tc = t + 1;
            float v = 0.f;
#pragma unroll
            for (int z = 0; z < ZC; z++) v += g_cbp[(size_t)z * (Bb * N3) + b * N3 + D2 + d];
            float v2 = 0.f;
#pragma unroll
            for (int z = 0; z < Z2; z++) v2 += g_P2p[(size_t)z * (Bb * Tt * Dd) + (b * Tt + tc) * Dd + d];
            v += v2 + bcq[d] + g_bp2[tc * Dd + d];
            us[d] = v * Wca[d];
            __syncthreads();

            const float* cb = ctx + (size_t)b * Ss * Dd;
            const float4* us4 = (const float4*)us;
            for (int s = wrp; s < Ss; s += 16) {
                const float4* row4 = (const float4*)(cb + (size_t)s * Dd);
                float part = 0.f;
#pragma unroll
                for (int d4 = lane; d4 < Dd / 4; d4 += 32) {
                    float4 a = row4[d4], u = us4[d4];
                    part += a.x * u.x + a.y * u.y + a.z * u.z + a.w * u.w;
                }
                part = warp_sum(part);
                if (lane == 0) sl[s] = part;
            }
            __syncthreads();
            if (wrp == 0) {
                float mx = -1e30f;
                for (int i = lane; i < Ss; i += 32) mx = fmaxf(mx, sl[i]);
                mx = warp_max(mx);
                float sm = 0.f;
                for (int i = lane; i < Ss; i += 32) { float e = __expf(sl[i] - mx); sl[i] = e; sm += e; }
                sm = warp_sum(sm);
                if (lane == 0) red[0] = 1.f / sm;
            }
            __syncthreads();
            const float inv = red[0];
            float a = 0.f;
#pragma unroll 8
            for (int s = 0; s < Ss; s++) a += sl[s] * cb[(size_t)s * Dd + d];
            g_c[b * Dd + d] = a * inv;
        }
        grid_sync(gen);

        // ---- G(t+1): comb(c(t+1)) [48 jobs] + write(t) [64 jobs if t>=0] ----
        if (t + 1 < Tt) {
            int njobs = (t >= 0) ? 112 : 48;
            for (int j = bid; j < njobs; j += NB) {
                if (j < 48) do_comb(j / 12, j % 12, Wrc, Wra, Wcq, sht);
                else { int r = j - 48; do_write(t, r >> 3, r & 7, Wwc, sht); }
            }
        } else {
            // final write(Tt-1): only the m-half (nI 0..3) is needed for out
            for (int j = bid; j < 32; j += NB) do_write(Tt - 1, j >> 2, j & 3, Wwc, sht);
        }
        grid_sync(gen);
    }

    // ===== final output: reduce write(11) partials (fpB, Tt-1 odd) =====
    {
        float v = 0.f;
#pragma unroll
        for (int z = 0; z < ZW; z++) v += g_fpB[(size_t)z * (Bb * D2) + bid * D2 + tid];
        out[bid * Dd + tid] = v + bwc[tid];
    }
}

// ---------------- host ----------------
extern "C" void kernel_launch(void* const* d_in, const int* in_sizes, int n_in,
                              void* d_out, int out_size)
{
    const float* ctx  = (const float*)d_in[0];
    const float* q    = (const float*)d_in[1];
    const float* kten = (const float*)d_in[2];
    const float* mem0 = (const float*)d_in[3];
    const float* ctrl0= (const float*)d_in[4];
    const float* Wp   = (const float*)d_in[5];
    const float* bp   = (const float*)d_in[6];
    const float* Wcq  = (const float*)d_in[7];
    const float* bcq  = (const float*)d_in[8];
    const float* Wca  = (const float*)d_in[9];
    const float* Wrm  = (const float*)d_in[11];
    const float* brm  = (const float*)d_in[12];
    const float* Wrc  = (const float*)d_in[13];
    const float* Wra  = (const float*)d_in[15];
    const float* Wwc  = (const float*)d_in[17];
    const float* bwc  = (const float*)d_in[18];
    float* out = (float*)d_out;

    cudaFuncSetAttribute(mac_mega, cudaFuncAttributeMaxDynamicSharedMemorySize, SMEM_TOTAL);
    mac_mega<<<NB, NTH, SMEM_TOTAL>>>(ctx, q, kten, mem0, ctrl0, Wp, bp, Wcq, bcq, Wca,
                                      Wrm, brm, Wrc, Wra, Wwc, bwc, out);

    (void)in_sizes; (void)n_in; (void)out_size;
}